// round 1
// baseline (speedup 1.0000x reference)
#include <cuda_runtime.h>

#define GROUPS 4
#define KCODES 1024
#define DIM 64
#define CT 32          // codes per smem tile (per group)
#define TOK_PER_BLK 64

// scratch (no allocations allowed)
__device__ double g_loss_acc;
__device__ float  g_csq[GROUPS * KCODES];

typedef unsigned long long u64t;

__device__ __forceinline__ u64t pack2(float a, float b) {
    u64t r;
    asm("mov.b64 %0, {%1, %2};" : "=l"(r) : "f"(a), "f"(b));
    return r;
}
__device__ __forceinline__ void unpack2(u64t p, float& a, float& b) {
    asm("mov.b64 {%0, %1}, %2;" : "=f"(a), "=f"(b) : "l"(p));
}
__device__ __forceinline__ u64t fma2(u64t a, u64t b, u64t c) {
    u64t d;
    asm("fma.rn.f32x2 %0, %1, %2, %3;" : "=l"(d) : "l"(a), "l"(b), "l"(c));
    return d;
}

// Kernel 1: zero loss accumulator, precompute ||c_k||^2 per (group, code)
__global__ void vq_prep_kernel(const float* __restrict__ cb) {
    int idx = blockIdx.x * blockDim.x + threadIdx.x;
    if (idx == 0) g_loss_acc = 0.0;
    if (idx < GROUPS * KCODES) {
        const float4* p = (const float4*)(cb + (size_t)idx * DIM);
        float s = 0.f;
#pragma unroll
        for (int i = 0; i < DIM / 4; i++) {
            float4 v = p[i];
            s = __fadd_rn(s, __fmul_rn(v.x, v.x));
            s = __fadd_rn(s, __fmul_rn(v.y, v.y));
            s = __fadd_rn(s, __fmul_rn(v.z, v.z));
            s = __fadd_rn(s, __fmul_rn(v.w, v.w));
        }
        g_csq[idx] = s;
    }
}

// Kernel 2: main VQ — one thread per (token, group)
__global__ void __launch_bounds__(256, 2)
vq_main_kernel(const float* __restrict__ lat, const float* __restrict__ cb,
               float* __restrict__ out, int ntok) {
    __shared__ float  s_c[GROUPS * CT * DIM];   // 32 KB codebook tile
    __shared__ float  s_q[GROUPS * CT];         // csq tile
    __shared__ double s_red[8];

    const int tid = threadIdx.x;
    const int g   = tid >> 6;          // warps are group-uniform -> LDS broadcast
    const int tl  = tid & 63;
    int token = blockIdx.x * TOK_PER_BLK + tl;
    const bool valid = (token < ntok);
    if (!valid) token = ntok - 1;      // clamp; stores/loss predicated

    const float4* xg = (const float4*)(lat + (size_t)token * (GROUPS * DIM) + g * DIM);

    // Load x, compute ||x||^2 with the reference's sequential fp32 rounding
    // (explicit __fadd_rn/__fmul_rn: no FMA contraction allowed here).
    u64t  xp[DIM / 2];
    float xsq = 0.f;
#pragma unroll
    for (int i = 0; i < DIM / 4; i++) {
        float4 v = xg[i];
        xsq = __fadd_rn(xsq, __fmul_rn(v.x, v.x));
        xsq = __fadd_rn(xsq, __fmul_rn(v.y, v.y));
        xsq = __fadd_rn(xsq, __fmul_rn(v.z, v.z));
        xsq = __fadd_rn(xsq, __fmul_rn(v.w, v.w));
        xp[2 * i]     = pack2(v.x, v.y);
        xp[2 * i + 1] = pack2(v.z, v.w);
    }

    float best = 3.4e38f;
    int   bi   = 0;

    for (int kt = 0; kt < KCODES / CT; kt++) {
        // Cooperative tile load: [4 groups][CT codes][64 dims], coalesced float4
        {
            const float4* src = (const float4*)cb;
            float4*       dst = (float4*)s_c;
#pragma unroll
            for (int r = 0; r < (GROUPS * CT * DIM / 4) / 256; r++) {
                int i  = tid + r * 256;          // 0..2047
                int d4 = i & 15;
                int kc = (i >> 4) & (CT - 1);
                int gg = i >> 9;
                dst[i] = src[(size_t)gg * KCODES * (DIM / 4)
                             + (size_t)(kt * CT + kc) * (DIM / 4) + d4];
            }
            if (tid < GROUPS * CT)
                s_q[tid] = g_csq[(tid >> 5) * KCODES + kt * CT + (tid & 31)];
        }
        __syncthreads();

        const ulonglong2* cbase = (const ulonglong2*)(s_c + g * CT * DIM);
#pragma unroll 4
        for (int kc = 0; kc < CT; kc++) {
            const ulonglong2* cp = cbase + kc * (DIM / 4);
            u64t a0 = 0ull, a1 = 0ull, a2 = 0ull, a3 = 0ull;
#pragma unroll
            for (int j = 0; j < DIM / 4; j += 2) {
                ulonglong2 c0 = cp[j];
                ulonglong2 c1 = cp[j + 1];
                a0 = fma2(xp[2 * j],     c0.x, a0);
                a1 = fma2(xp[2 * j + 1], c0.y, a1);
                a2 = fma2(xp[2 * j + 2], c1.x, a2);
                a3 = fma2(xp[2 * j + 3], c1.y, a3);
            }
            float f0, f1, f2, f3, f4, f5, f6, f7;
            unpack2(a0, f0, f1); unpack2(a1, f2, f3);
            unpack2(a2, f4, f5); unpack2(a3, f6, f7);
            float dot = ((f0 + f2) + (f4 + f6)) + ((f1 + f3) + (f5 + f7));
            // Reference rounding sequence: (xsq - 2*dot) then + csq
            float dist = __fadd_rn(__fsub_rn(xsq, __fmul_rn(2.f, dot)),
                                   s_q[g * CT + kc]);
            if (dist < best) { best = dist; bi = kt * CT + kc; }
        }
        __syncthreads();
    }

    // Epilogue: gather winning codeword, write x + (q - x), accumulate (q-x)^2
    const float4* cq = (const float4*)(cb + ((size_t)g * KCODES + bi) * DIM);
    float4* og = (float4*)(out + (size_t)token * (GROUPS * DIM) + g * DIM);
    float lsum = 0.f;
    if (valid) {
#pragma unroll
        for (int i = 0; i < DIM / 4; i++) {
            float4 xv = xg[i];
            float4 cv = cq[i];
            float4 o;
            float t;
            t = __fsub_rn(cv.x, xv.x); o.x = __fadd_rn(xv.x, t); lsum = __fmaf_rn(t, t, lsum);
            t = __fsub_rn(cv.y, xv.y); o.y = __fadd_rn(xv.y, t); lsum = __fmaf_rn(t, t, lsum);
            t = __fsub_rn(cv.z, xv.z); o.z = __fadd_rn(xv.z, t); lsum = __fmaf_rn(t, t, lsum);
            t = __fsub_rn(cv.w, xv.w); o.w = __fadd_rn(xv.w, t); lsum = __fmaf_rn(t, t, lsum);
            og[i] = o;
        }
    }

    // Block loss reduction -> one double atomic per block
#pragma unroll
    for (int off = 16; off; off >>= 1)
        lsum += __shfl_xor_sync(0xFFFFFFFFu, lsum, off);
    if ((tid & 31) == 0) s_red[tid >> 5] = (double)lsum;
    __syncthreads();
    if (tid == 0) {
        double b = 0.0;
#pragma unroll
        for (int i = 0; i < 8; i++) b += s_red[i];
        atomicAdd(&g_loss_acc, b);
    }
}

// Kernel 3: finalize loss
__global__ void vq_finish_kernel(float* __restrict__ out, long long loss_idx,
                                 long long count) {
    double m  = g_loss_acc / (double)count;
    float  mf = (float)m;
    out[loss_idx] = __fadd_rn(__fmul_rn(mf, 0.25f), mf);  // beta*commit + embed
}

extern "C" void kernel_launch(void* const* d_in, const int* in_sizes, int n_in,
                              void* d_out, int out_size) {
    const float* lat = (const float*)d_in[0];
    const float* cb  = (const float*)d_in[1];
    float* out = (float*)d_out;

    const int n_lat = in_sizes[0];               // 8388608
    const int ntok  = n_lat / (GROUPS * DIM);    // 32768

    vq_prep_kernel<<<(GROUPS * KCODES + 255) / 256, 256>>>(cb);

    int grid = (ntok + TOK_PER_BLK - 1) / TOK_PER_BLK;
    vq_main_kernel<<<grid, 256>>>(lat, cb, out, ntok);

    vq_finish_kernel<<<1, 1>>>(out, (long long)out_size - 1, (long long)n_lat);
}

// round 2
// speedup vs baseline: 1.7465x; 1.7465x over previous
#include <cuda_runtime.h>

#define GROUPS 4
#define KCODES 1024
#define DIM 64
#define TOK_BLK 128        // tokens per block (one group per block)
#define TILE_K 128         // codes per smem tile
#define NTILES (KCODES / TILE_K)
// thread tile: 4 tokens x 16 codes; block = 256 threads = 8 ci x 32 ti

__device__ double g_loss_acc;
__device__ float  g_csq[GROUPS * KCODES];

typedef unsigned long long u64t;

__device__ __forceinline__ u64t pack2(float a, float b) {
    u64t r; asm("mov.b64 %0, {%1, %2};" : "=l"(r) : "f"(a), "f"(b)); return r;
}
__device__ __forceinline__ void unpack2(u64t p, float& a, float& b) {
    asm("mov.b64 {%0, %1}, %2;" : "=f"(a), "=f"(b) : "l"(p));
}
__device__ __forceinline__ u64t fma2(u64t a, u64t b, u64t c) {
    u64t d; asm("fma.rn.f32x2 %0, %1, %2, %3;" : "=l"(d) : "l"(a), "l"(b), "l"(c)); return d;
}
__device__ __forceinline__ u64t add2(u64t a, u64t b) {
    u64t d; asm("add.rn.f32x2 %0, %1, %2;" : "=l"(d) : "l"(a), "l"(b)); return d;
}

// Kernel 1: zero loss accumulator, precompute ||c_k||^2  (bitwise-identical to R1)
__global__ void vq_prep_kernel(const float* __restrict__ cb) {
    int idx = blockIdx.x * blockDim.x + threadIdx.x;
    if (idx == 0) g_loss_acc = 0.0;
    if (idx < GROUPS * KCODES) {
        const float4* p = (const float4*)(cb + (size_t)idx * DIM);
        float s = 0.f;
#pragma unroll
        for (int i = 0; i < DIM / 4; i++) {
            float4 v = p[i];
            s = __fadd_rn(s, __fmul_rn(v.x, v.x));
            s = __fadd_rn(s, __fmul_rn(v.y, v.y));
            s = __fadd_rn(s, __fmul_rn(v.z, v.z));
            s = __fadd_rn(s, __fmul_rn(v.w, v.w));
        }
        g_csq[idx] = s;
    }
}

// Dynamic smem layout (bytes):
//  x_s   [0,      32768)   : x dim-major [64 d][128 tok], XOR-swizzled 16B chunks
//  c_s   [32768,  65536)   : codebook tile dim-major [64 d][128 k], swizzled
//  csq_s [65536,  66048)   : 128 floats
//  xsq_s [66048,  66560)   : 128 floats
//  red_  (inside c_s after last tile)
//  sred  [66560,  66624)   : 8 doubles
#define SMEM_BYTES 66624

__global__ void __launch_bounds__(256, 2)
vq_main_kernel(const float* __restrict__ lat, const float* __restrict__ cb,
               float* __restrict__ out, int ntok) {
    extern __shared__ char smem[];
    float*  x_s   = (float*)smem;                    // 64*128 floats
    float*  c_s   = (float*)(smem + 32768);          // 64*128 floats
    float*  csq_s = (float*)(smem + 65536);          // 128
    float*  xsq_s = (float*)(smem + 66048);          // 128
    double* sred  = (double*)(smem + 66560);

    const int tid = threadIdx.x;
    const int ti  = tid & 31;          // token quad id: tokens 4ti..4ti+3
    const int ci  = tid >> 5;          // code block id: codes 16ci..16ci+15 (per tile)
    const int b   = blockIdx.x;
    const int g   = b & 3;
    const int tok0 = (b >> 2) * TOK_BLK;

    const float* latg = lat + (size_t)g * DIM;       // + token*256 later
    const float* cbg  = cb + (size_t)g * KCODES * DIM;

    // ---- stage x into smem, dim-major with swizzle: x_s[4q+j][t] at
    //      float idx (4q+j)*128 + ((t>>2)^(q&7))*4 + (t&3)
    {
        const int q  = tid & 15;
        const int tb = tid >> 4;       // 0..15
#pragma unroll
        for (int it = 0; it < 8; it++) {
            int t = tb + 16 * it;
            int tok = tok0 + t; if (tok >= ntok) tok = ntok - 1;
            float4 v = *(const float4*)(latg + (size_t)tok * (GROUPS * DIM) + 4 * q);
            int chunk = ((t >> 2) ^ (q & 7)) * 4 + (t & 3);
            x_s[(4 * q + 0) * 128 + chunk] = v.x;
            x_s[(4 * q + 1) * 128 + chunk] = v.y;
            x_s[(4 * q + 2) * 128 + chunk] = v.z;
            x_s[(4 * q + 3) * 128 + chunk] = v.w;
        }
    }
    // ---- xsq per token: EXACT R1 rounding sequence, from global (L2-hot)
    if (tid < TOK_BLK) {
        int tok = tok0 + tid; if (tok >= ntok) tok = ntok - 1;
        const float4* xg = (const float4*)(latg + (size_t)tok * (GROUPS * DIM));
        float s = 0.f;
#pragma unroll
        for (int i = 0; i < DIM / 4; i++) {
            float4 v = xg[i];
            s = __fadd_rn(s, __fmul_rn(v.x, v.x));
            s = __fadd_rn(s, __fmul_rn(v.y, v.y));
            s = __fadd_rn(s, __fmul_rn(v.z, v.z));
            s = __fadd_rn(s, __fmul_rn(v.w, v.w));
        }
        xsq_s[tid] = s;
    }
    __syncthreads();

    u64t xsqd[4];
#pragma unroll
    for (int t = 0; t < 4; t++) {
        float v = xsq_s[4 * ti + t];
        xsqd[t] = pack2(v, v);
    }
    const u64t NEG2 = pack2(-2.f, -2.f);

    float best[4] = {3.4e38f, 3.4e38f, 3.4e38f, 3.4e38f};
    int   bidx[4] = {0, 0, 0, 0};

    for (int tile = 0; tile < NTILES; tile++) {
        // ---- load codebook tile (TILE_K codes x 64 dims), transpose to dim-major
        {
            const int q  = tid & 15;
            const int kb = tid >> 4;   // 0..15
#pragma unroll
            for (int it = 0; it < 8; it++) {
                int k = kb + 16 * it;
                float4 v = *(const float4*)(cbg + (size_t)(tile * TILE_K + k) * DIM + 4 * q);
                int chunk = ((k >> 2) ^ (q & 7)) * 4 + (k & 3);
                c_s[(4 * q + 0) * 128 + chunk] = v.x;
                c_s[(4 * q + 1) * 128 + chunk] = v.y;
                c_s[(4 * q + 2) * 128 + chunk] = v.z;
                c_s[(4 * q + 3) * 128 + chunk] = v.w;
            }
            if (tid < TILE_K)
                csq_s[tid] = g_csq[g * KCODES + tile * TILE_K + tid];
        }
        __syncthreads();

        // ---- accumulate dots: acc[t][p] packs codes (16ci+2p, 16ci+2p+1)
        u64t acc[4][8];
#pragma unroll
        for (int t = 0; t < 4; t++)
#pragma unroll
            for (int p = 0; p < 8; p++) acc[t][p] = 0ull;

#pragma unroll 2
        for (int q = 0; q < 16; q++) {
            const int s = q & 7;
            const int xc = ti ^ s;                 // 16B chunk idx for this thread's tokens
            const int cbase = 4 * ci;
#pragma unroll
            for (int j = 0; j < 4; j++) {
                const int d = 4 * q + j;
                float4 xv = ((const float4*)x_s)[d * 32 + xc];
                u64t xd0 = pack2(xv.x, xv.x);
                u64t xd1 = pack2(xv.y, xv.y);
                u64t xd2 = pack2(xv.z, xv.z);
                u64t xd3 = pack2(xv.w, xv.w);
                const ulonglong2* crow = (const ulonglong2*)c_s + d * 32;
                ulonglong2 c0 = crow[(cbase + 0) ^ s];
                ulonglong2 c1 = crow[(cbase + 1) ^ s];
                ulonglong2 c2 = crow[(cbase + 2) ^ s];
                ulonglong2 c3 = crow[(cbase + 3) ^ s];
                // map loaded float4s (code quads) -> code-pair u64s in ascending order
                u64t cp[8];
                cp[0] = c0.x; cp[1] = c0.y; cp[2] = c1.x; cp[3] = c1.y;
                cp[4] = c2.x; cp[5] = c2.y; cp[6] = c3.x; cp[7] = c3.y;
#pragma unroll
                for (int p = 0; p < 8; p++) {
                    acc[0][p] = fma2(xd0, cp[p], acc[0][p]);
                    acc[1][p] = fma2(xd1, cp[p], acc[1][p]);
                    acc[2][p] = fma2(xd2, cp[p], acc[2][p]);
                    acc[3][p] = fma2(xd3, cp[p], acc[3][p]);
                }
            }
        }

        // NOTE: loaded chunk (cbase+m)^s holds LOGICAL chunk (cbase+m)^s^s?? No:
        // physical slot (l^s) holds logical l; we read physical (cbase+m)^s which
        // holds logical ((cbase+m)^s)^s = cbase+m. Correct: reading physical index
        // (cbase+m)^s returns logical chunk cbase+m. (Store wrote logical chunk
        // t>>2 at physical (t>>2)^s.)  -- wait, store wrote at physical (l)^s? It
        // wrote chunk' = l ^ s, i.e. physical = logical ^ s, so logical l is at
        // physical l^s, and we read physical (cbase+m)^s = logical cbase+m. OK.

        // ---- per-tile packed dist + argmin (codes ascending => strict '<'
        //      keeps lowest index on exact ties, matching jnp.argmin)
        const u64t* csq2 = (const u64t*)csq_s;
#pragma unroll
        for (int p = 0; p < 8; p++) {
            u64t cs = csq2[8 * ci + p];
            int kidx = tile * TILE_K + 16 * ci + 2 * p;
#pragma unroll
            for (int t = 0; t < 4; t++) {
                u64t pk = fma2(acc[t][p], NEG2, xsqd[t]);  // round(xsq - 2*dot): 2*dot exact
                pk = add2(pk, cs);                          // + csq, same rounding as R1
                float d0, d1; unpack2(pk, d0, d1);
                if (d0 < best[t]) { best[t] = d0; bidx[t] = kidx; }
                if (d1 < best[t]) { best[t] = d1; bidx[t] = kidx + 1; }
            }
        }
        __syncthreads();
    }

    // ---- block-wide argmin: 8 ci-candidates per token, idx tie-break (ranges interleave)
    float* red_d = c_s;                 // [128][8]
    int*   red_i = (int*)(c_s + 1024);  // [128][8]
#pragma unroll
    for (int t = 0; t < 4; t++) {
        red_d[(4 * ti + t) * 8 + ci] = best[t];
        red_i[(4 * ti + t) * 8 + ci] = bidx[t];
    }
    __syncthreads();

    float lsum = 0.f;
    if (tid < TOK_BLK) {
        float bv = red_d[tid * 8];
        int   bi = red_i[tid * 8];
#pragma unroll
        for (int c = 1; c < 8; c++) {
            float d = red_d[tid * 8 + c];
            int   i = red_i[tid * 8 + c];
            if (d < bv || (d == bv && i < bi)) { bv = d; bi = i; }
        }
        int tok = tok0 + tid;
        bool valid = (tok < ntok);
        if (!valid) tok = ntok - 1;
        const float4* cq = (const float4*)(cbg + (size_t)bi * DIM);
        const float4* xg = (const float4*)(latg + (size_t)tok * (GROUPS * DIM));
        float4* stage = (float4*)x_s;   // reuse x_s as output staging [tok][16 f4]
        if (valid) {
#pragma unroll
            for (int i = 0; i < DIM / 4; i++) {
                int f = (i + tid) & 15;      // stagger to avoid STS bank conflicts
                float4 xv = xg[f];
                float4 cv = cq[f];
                float4 o; float t2;
                t2 = __fsub_rn(cv.x, xv.x); o.x = __fadd_rn(xv.x, t2); lsum = __fmaf_rn(t2, t2, lsum);
                t2 = __fsub_rn(cv.y, xv.y); o.y = __fadd_rn(xv.y, t2); lsum = __fmaf_rn(t2, t2, lsum);
                t2 = __fsub_rn(cv.z, xv.z); o.z = __fadd_rn(xv.z, t2); lsum = __fmaf_rn(t2, t2, lsum);
                t2 = __fsub_rn(cv.w, xv.w); o.w = __fadd_rn(xv.w, t2); lsum = __fmaf_rn(t2, t2, lsum);
                stage[tid * 16 + f] = o;
            }
        }
    }

    // loss reduction (warps 0-3 hold per-token sums)
#pragma unroll
    for (int off = 16; off; off >>= 1)
        lsum += __shfl_xor_sync(0xFFFFFFFFu, lsum, off);
    if ((tid & 31) == 0) sred[tid >> 5] = (double)lsum;
    __syncthreads();
    if (tid == 0) {
        double acc2 = 0.0;
#pragma unroll
        for (int i = 0; i < 8; i++) acc2 += sred[i];
        atomicAdd(&g_loss_acc, acc2);
    }

    // ---- coalesced output store from staging
    {
        const float4* stage = (const float4*)x_s;
#pragma unroll
        for (int r = 0; r < 8; r++) {
            int li = tid + r * 256;            // 0..2047
            int t  = li >> 4;
            int f  = li & 15;
            int tok = tok0 + t;
            if (tok < ntok)
                *(float4*)(out + (size_t)tok * (GROUPS * DIM) + g * DIM + 4 * f) =
                    stage[li];
        }
    }
}

__global__ void vq_finish_kernel(float* __restrict__ out, long long loss_idx,
                                 long long count) {
    double m  = g_loss_acc / (double)count;
    float  mf = (float)m;
    out[loss_idx] = __fadd_rn(__fmul_rn(mf, 0.25f), mf);
}

extern "C" void kernel_launch(void* const* d_in, const int* in_sizes, int n_in,
                              void* d_out, int out_size) {
    const float* lat = (const float*)d_in[0];
    const float* cb  = (const float*)d_in[1];
    float* out = (float*)d_out;

    const int n_lat = in_sizes[0];               // 8388608
    const int ntok  = n_lat / (GROUPS * DIM);    // 32768

    cudaFuncSetAttribute(vq_main_kernel,
                         cudaFuncAttributeMaxDynamicSharedMemorySize, SMEM_BYTES);

    vq_prep_kernel<<<(GROUPS * KCODES + 255) / 256, 256>>>(cb);

    int tokBlocks = (ntok + TOK_BLK - 1) / TOK_BLK;
    vq_main_kernel<<<tokBlocks * GROUPS, 256, SMEM_BYTES>>>(lat, cb, out, ntok);

    vq_finish_kernel<<<1, 1>>>(out, (long long)out_size - 1, (long long)n_lat);
}